// round 1
// baseline (speedup 1.0000x reference)
#include <cuda_runtime.h>
#include <cuda_bf16.h>
#include <math.h>

// QuantumNet fused kernel:
//  pre GEMM [B,512]x[512,4] -> angles -> 4-qubit circuit (algebraically
//  collapsed: product state + compile-time CNOT permutation + U3 folded
//  into Z-expectation quadratic form) -> post GEMM [B,4]x[4,2].

#define KDIM 512
#define NQ 4
#define ROWS 128          // rows (batch elements) per block
#define THREADS 128
#define KTILE 64
#define XS_STRIDE 68      // 64 + 4 pad: conflict-free LDS.128 / STS.128

__global__ __launch_bounds__(THREADS)
void qnet_kernel(const float* __restrict__ x,
                 const float* __restrict__ pre_w,
                 const float* __restrict__ pre_b,
                 const float* __restrict__ u3p,
                 const float* __restrict__ post_w,
                 const float* __restrict__ post_b,
                 float* __restrict__ out, int B)
{
    __shared__ float wts[KDIM * 4];          // [k][q] transposed weights, 8KB
    __shared__ float xs[ROWS * XS_STRIDE];   // input tile, ~34KB

    const int tid  = threadIdx.x;
    const int row0 = blockIdx.x * ROWS;
    const int row  = row0 + tid;

    // Transpose pre_w [4][512] -> wts[k*4+q]
    #pragma unroll
    for (int i = tid; i < KDIM * 4; i += THREADS) {
        int q = i >> 9;        // /512
        int k = i & (KDIM - 1);
        wts[k * 4 + q] = pre_w[i];
    }

    float acc0 = 0.f, acc1 = 0.f, acc2 = 0.f, acc3 = 0.f;

    for (int kt = 0; kt < KDIM / KTILE; ++kt) {
        const int kbase = kt * KTILE;
        // Load 128 rows x 64 cols tile, coalesced float4
        #pragma unroll
        for (int i = 0; i < 16; ++i) {
            int f = tid + i * THREADS;   // 0..2047
            int r = f >> 4;              // 0..127
            int c = f & 15;              // float4 col 0..15
            int gr = row0 + r;
            float4 v = make_float4(0.f, 0.f, 0.f, 0.f);
            if (gr < B)
                v = *(const float4*)&x[(size_t)gr * KDIM + kbase + c * 4];
            *(float4*)&xs[r * XS_STRIDE + c * 4] = v;
        }
        __syncthreads();

        #pragma unroll
        for (int k = 0; k < KTILE; k += 4) {
            float4 xv = *(const float4*)&xs[tid * XS_STRIDE + k];
            float4 w0 = *(const float4*)&wts[(kbase + k + 0) * 4];
            float4 w1 = *(const float4*)&wts[(kbase + k + 1) * 4];
            float4 w2 = *(const float4*)&wts[(kbase + k + 2) * 4];
            float4 w3 = *(const float4*)&wts[(kbase + k + 3) * 4];
            acc0 = fmaf(xv.x, w0.x, acc0); acc1 = fmaf(xv.x, w0.y, acc1);
            acc2 = fmaf(xv.x, w0.z, acc2); acc3 = fmaf(xv.x, w0.w, acc3);
            acc0 = fmaf(xv.y, w1.x, acc0); acc1 = fmaf(xv.y, w1.y, acc1);
            acc2 = fmaf(xv.y, w1.z, acc2); acc3 = fmaf(xv.y, w1.w, acc3);
            acc0 = fmaf(xv.z, w2.x, acc0); acc1 = fmaf(xv.z, w2.y, acc1);
            acc2 = fmaf(xv.z, w2.z, acc2); acc3 = fmaf(xv.z, w2.w, acc3);
            acc0 = fmaf(xv.w, w3.x, acc0); acc1 = fmaf(xv.w, w3.y, acc1);
            acc2 = fmaf(xv.w, w3.z, acc2); acc3 = fmaf(xv.w, w3.w, acc3);
        }
        __syncthreads();
    }

    if (row >= B) return;

    float pre[4];
    pre[0] = acc0 + pre_b[0];
    pre[1] = acc1 + pre_b[1];
    pre[2] = acc2 + pre_b[2];
    pre[3] = acc3 + pre_b[3];

    // Per-qubit single-qubit state after H, RY(atan t), RZ(atan t^2):
    //   alpha = (c-s)/sqrt2 * e^{-i rz/2},  beta = (c+s)/sqrt2 * e^{+i rz/2}
    // Using cos(atan t) = rsqrt(1+t^2) + stable half-angle identities.
    float aR[4], aI[4], bR[4], bI[4];
    const float HALF_PI = 1.5707963267948966f;
    const float INV_SQRT2 = 0.7071067811865476f;
    #pragma unroll
    for (int q = 0; q < 4; ++q) {
        float t  = tanhf(pre[q] * 0.1f) * HALF_PI;     // q_in
        // RY half-angle
        float cr = rsqrtf(fmaf(t, t, 1.f));            // cos(ry)
        float sr = t * cr;                             // sin(ry)
        float c2 = sqrtf(0.5f * (1.f + cr));           // cos(ry/2)
        float s2 = 0.5f * sr * __fdividef(1.f, c2);    // sin(ry/2)
        // RZ half-angle, u = t^2 >= 0
        float u  = t * t;
        float cz = rsqrtf(fmaf(u, u, 1.f));            // cos(rz)
        float szf = u * cz;                            // sin(rz)
        float ch = sqrtf(0.5f * (1.f + cz));           // cos(rz/2)
        float sh = 0.5f * szf * __fdividef(1.f, ch);   // sin(rz/2)
        float Aa = (c2 - s2) * INV_SQRT2;
        float Bb = (c2 + s2) * INV_SQRT2;
        aR[q] = Aa * ch;  aI[q] = -Aa * sh;
        bR[q] = Bb * ch;  bI[q] =  Bb * sh;
    }

    // top[h] = f_q0[h>>1] * f_q1[h&1];  bot[l] = f_q2[l>>1] * f_q3[l&1]
    float tR[4], tI[4], uR[4], uI[4];
    #pragma unroll
    for (int h = 0; h < 4; ++h) {
        int j0 = h >> 1, j1 = h & 1;
        float r0 = j0 ? bR[0] : aR[0], i0 = j0 ? bI[0] : aI[0];
        float r1 = j1 ? bR[1] : aR[1], i1 = j1 ? bI[1] : aI[1];
        tR[h] = r0 * r1 - i0 * i1;
        tI[h] = r0 * i1 + i0 * r1;
        float r2 = j0 ? bR[2] : aR[2], i2 = j0 ? bI[2] : aI[2];
        float r3 = j1 ? bR[3] : aR[3], i3 = j1 ? bI[3] : aI[3];
        uR[h] = r2 * r3 - i2 * i3;
        uI[h] = r2 * i3 + i2 * r3;
    }

    // Post-CNOT state: A[i] = psi[sigma(i)], sigma = composition of both
    // CNOT rings (GF(2)-linear, compile-time constant).
    float AR[16], AI[16], NR[16];
    #pragma unroll
    for (int i = 0; i < 16; ++i) {
        int a_ = (i >> 3) & 1, b_ = (i >> 2) & 1, c_ = (i >> 1) & 1, d_ = i & 1;
        int s  = ((a_ ^ b_ ^ c_) << 3) | ((a_ ^ c_ ^ d_) << 2)
               | ((a_ ^ b_ ^ d_) << 1) | (a_ ^ b_);
        int hi = s >> 2, lo = s & 3;
        AR[i] = tR[hi] * uR[lo] - tI[hi] * uI[lo];
        AI[i] = tR[hi] * uI[lo] + tI[hi] * uR[lo];
        NR[i] = AR[i] * AR[i] + AI[i] * AI[i];
    }

    // U3 folded into M_q = U3_q^dag Z U3_q = [[cos th, -sin th e^{i la}], [conj, -cos th]]
    float ct4[4], mr4[4], mi4[4];
    #pragma unroll
    for (int q = 0; q < 4; ++q) {
        float th = u3p[q * 3 + 0];
        float la = u3p[q * 3 + 2];
        float st_, ct_, sl_, cl_;
        __sincosf(th, &st_, &ct_);
        __sincosf(la, &sl_, &cl_);
        ct4[q] = ct_;
        mr4[q] = -st_ * cl_;
        mi4[q] = -st_ * sl_;
    }

    // E_q = sum over pairs: cos(th)(n0-n1) + 2 Re(M01 * conj(A0) A1)
    float E[4];
    #pragma unroll
    for (int q = 0; q < 4; ++q) {
        const int p = 3 - q;   // bit position of qubit q
        float Sn = 0.f, Szr = 0.f, Szi = 0.f;
        #pragma unroll
        for (int m = 0; m < 8; ++m) {
            int lowmask = (1 << p) - 1;
            int i0 = ((m & ~lowmask) << 1) | (m & lowmask);
            int i1 = i0 | (1 << p);
            Sn  += NR[i0] - NR[i1];
            Szr += AR[i0] * AR[i1] + AI[i0] * AI[i1];
            Szi += AR[i0] * AI[i1] - AI[i0] * AR[i1];
        }
        E[q] = ct4[q] * Sn + 2.f * (mr4[q] * Szr - mi4[q] * Szi);
    }

    float o0 = post_b[0], o1 = post_b[1];
    #pragma unroll
    for (int q = 0; q < 4; ++q) {
        o0 = fmaf(post_w[q],     E[q], o0);
        o1 = fmaf(post_w[4 + q], E[q], o1);
    }
    float2 res; res.x = o0; res.y = o1;
    ((float2*)out)[row] = res;
}

extern "C" void kernel_launch(void* const* d_in, const int* in_sizes, int n_in,
                              void* d_out, int out_size) {
    const float* x      = (const float*)d_in[0];
    const float* pre_w  = (const float*)d_in[1];
    const float* pre_b  = (const float*)d_in[2];
    const float* u3p    = (const float*)d_in[3];
    const float* post_w = (const float*)d_in[4];
    const float* post_b = (const float*)d_in[5];
    float* out = (float*)d_out;

    int B = in_sizes[0] / KDIM;
    int grid = (B + ROWS - 1) / ROWS;
    qnet_kernel<<<grid, THREADS>>>(x, pre_w, pre_b, u3p, post_w, post_b, out, B);
}

// round 3
// speedup vs baseline: 1.3009x; 1.3009x over previous
#include <cuda_runtime.h>
#include <cuda_bf16.h>
#include <cstdint>
#include <math.h>

// QuantumNet fused kernel, round 3: double-buffered cp.async pipeline
// (round-2 kernel with the missing <cstdint> include fixed).
// pre GEMM [B,512]x[512,4] -> angles -> collapsed 4-qubit circuit -> [B,4]x[4,2].

#define KDIM 512
#define ROWS 64           // rows per CTA
#define THREADS 64
#define KTILE 64
#define NTILES (KDIM / KTILE)   // 8
#define XS_STRIDE 68      // 64 + 4 pad (17 float4-granules, odd -> conflict-free)

__device__ __forceinline__ void cpasync16(float* dst_smem, const float* src) {
    unsigned int s = (unsigned int)__cvta_generic_to_shared(dst_smem);
    asm volatile("cp.async.cg.shared.global [%0], [%1], 16;\n" :: "r"(s), "l"(src));
}

__global__ __launch_bounds__(THREADS)
void qnet_kernel(const float* __restrict__ x,
                 const float* __restrict__ pre_w,
                 const float* __restrict__ pre_b,
                 const float* __restrict__ u3p,
                 const float* __restrict__ post_w,
                 const float* __restrict__ post_b,
                 float* __restrict__ out, int B)
{
    __shared__ float wts[KDIM * 4];                 // 8 KB, [k][q]
    __shared__ float xs[2][ROWS * XS_STRIDE];       // 2 x 17.4 KB

    const int tid  = threadIdx.x;
    const int row0 = blockIdx.x * ROWS;
    const int row  = row0 + tid;

    // Transpose pre_w [4][512] -> wts[k*4+q] (plain loads; covered by first sync)
    #pragma unroll
    for (int i = tid; i < KDIM * 4; i += THREADS) {
        int q = i >> 9;
        int k = i & (KDIM - 1);
        wts[k * 4 + q] = pre_w[i];
    }

    // --- cp.async tile loader: 64 rows x 16 float4 = 1024 float4, 16/thread
    auto issue_tile = [&](int kt, int stage) {
        const int kbase = kt * KTILE;
        #pragma unroll
        for (int i = 0; i < 16; ++i) {
            int f = tid + i * THREADS;   // 0..1023
            int r = f >> 4;              // 0..63
            int c = f & 15;              // float4 col
            int gr = row0 + r;
            if (gr < B)
                cpasync16(&xs[stage][r * XS_STRIDE + c * 4],
                          &x[(size_t)gr * KDIM + kbase + c * 4]);
        }
        asm volatile("cp.async.commit_group;\n" ::);
    };

    issue_tile(0, 0);
    issue_tile(1, 1);

    float acc0 = 0.f, acc1 = 0.f, acc2 = 0.f, acc3 = 0.f;

    #pragma unroll
    for (int kt = 0; kt < NTILES; ++kt) {
        if (kt < NTILES - 1)
            asm volatile("cp.async.wait_group 1;\n" ::);
        else
            asm volatile("cp.async.wait_group 0;\n" ::);
        __syncthreads();

        const int stage = kt & 1;
        const int kbase = kt * KTILE;
        #pragma unroll
        for (int k = 0; k < KTILE; k += 4) {
            float4 xv = *(const float4*)&xs[stage][tid * XS_STRIDE + k];
            float4 w0 = *(const float4*)&wts[(kbase + k + 0) * 4];
            float4 w1 = *(const float4*)&wts[(kbase + k + 1) * 4];
            float4 w2 = *(const float4*)&wts[(kbase + k + 2) * 4];
            float4 w3 = *(const float4*)&wts[(kbase + k + 3) * 4];
            acc0 = fmaf(xv.x, w0.x, acc0); acc1 = fmaf(xv.x, w0.y, acc1);
            acc2 = fmaf(xv.x, w0.z, acc2); acc3 = fmaf(xv.x, w0.w, acc3);
            acc0 = fmaf(xv.y, w1.x, acc0); acc1 = fmaf(xv.y, w1.y, acc1);
            acc2 = fmaf(xv.y, w1.z, acc2); acc3 = fmaf(xv.y, w1.w, acc3);
            acc0 = fmaf(xv.z, w2.x, acc0); acc1 = fmaf(xv.z, w2.y, acc1);
            acc2 = fmaf(xv.z, w2.z, acc2); acc3 = fmaf(xv.z, w2.w, acc3);
            acc0 = fmaf(xv.w, w3.x, acc0); acc1 = fmaf(xv.w, w3.y, acc1);
            acc2 = fmaf(xv.w, w3.z, acc2); acc3 = fmaf(xv.w, w3.w, acc3);
        }
        __syncthreads();   // stage consumed; safe to overwrite

        if (kt + 2 < NTILES)
            issue_tile(kt + 2, stage);
    }

    if (row >= B) return;

    float pre[4];
    pre[0] = acc0 + pre_b[0];
    pre[1] = acc1 + pre_b[1];
    pre[2] = acc2 + pre_b[2];
    pre[3] = acc3 + pre_b[3];

    // Per-qubit state after H, RY(atan t), RZ(atan t^2):
    //   alpha = (c-s)/sqrt2 e^{-i rz/2}, beta = (c+s)/sqrt2 e^{+i rz/2}
    float aR[4], aI[4], bR[4], bI[4];
    const float HALF_PI = 1.5707963267948966f;
    const float INV_SQRT2 = 0.7071067811865476f;
    #pragma unroll
    for (int q = 0; q < 4; ++q) {
        float t  = tanhf(pre[q] * 0.1f) * HALF_PI;
        float cr = rsqrtf(fmaf(t, t, 1.f));
        float sr = t * cr;
        float c2 = sqrtf(0.5f * (1.f + cr));
        float s2 = 0.5f * sr * __fdividef(1.f, c2);
        float u  = t * t;
        float cz = rsqrtf(fmaf(u, u, 1.f));
        float szf = u * cz;
        float ch = sqrtf(0.5f * (1.f + cz));
        float sh = 0.5f * szf * __fdividef(1.f, ch);
        float Aa = (c2 - s2) * INV_SQRT2;
        float Bb = (c2 + s2) * INV_SQRT2;
        aR[q] = Aa * ch;  aI[q] = -Aa * sh;
        bR[q] = Bb * ch;  bI[q] =  Bb * sh;
    }

    float tR[4], tI[4], uR[4], uI[4];
    #pragma unroll
    for (int h = 0; h < 4; ++h) {
        int j0 = h >> 1, j1 = h & 1;
        float r0 = j0 ? bR[0] : aR[0], i0 = j0 ? bI[0] : aI[0];
        float r1 = j1 ? bR[1] : aR[1], i1 = j1 ? bI[1] : aI[1];
        tR[h] = r0 * r1 - i0 * i1;
        tI[h] = r0 * i1 + i0 * r1;
        float r2 = j0 ? bR[2] : aR[2], i2 = j0 ? bI[2] : aI[2];
        float r3 = j1 ? bR[3] : aR[3], i3 = j1 ? bI[3] : aI[3];
        uR[h] = r2 * r3 - i2 * i3;
        uI[h] = r2 * i3 + i2 * r3;
    }

    // Post-CNOT state via compile-time GF(2) permutation
    float AR[16], AI[16], NR[16];
    #pragma unroll
    for (int i = 0; i < 16; ++i) {
        int a_ = (i >> 3) & 1, b_ = (i >> 2) & 1, c_ = (i >> 1) & 1, d_ = i & 1;
        int s  = ((a_ ^ b_ ^ c_) << 3) | ((a_ ^ c_ ^ d_) << 2)
               | ((a_ ^ b_ ^ d_) << 1) | (a_ ^ b_);
        int hi = s >> 2, lo = s & 3;
        AR[i] = tR[hi] * uR[lo] - tI[hi] * uI[lo];
        AI[i] = tR[hi] * uI[lo] + tI[hi] * uR[lo];
        NR[i] = AR[i] * AR[i] + AI[i] * AI[i];
    }

    // U3 folded into M_q = U3^dag Z U3
    float ct4[4], mr4[4], mi4[4];
    #pragma unroll
    for (int q = 0; q < 4; ++q) {
        float th = u3p[q * 3 + 0];
        float la = u3p[q * 3 + 2];
        float st_, ct_, sl_, cl_;
        __sincosf(th, &st_, &ct_);
        __sincosf(la, &sl_, &cl_);
        ct4[q] = ct_;
        mr4[q] = -st_ * cl_;
        mi4[q] = -st_ * sl_;
    }

    float E[4];
    #pragma unroll
    for (int q = 0; q < 4; ++q) {
        const int p = 3 - q;
        float Sn = 0.f, Szr = 0.f, Szi = 0.f;
        #pragma unroll
        for (int m = 0; m < 8; ++m) {
            int lowmask = (1 << p) - 1;
            int i0 = ((m & ~lowmask) << 1) | (m & lowmask);
            int i1 = i0 | (1 << p);
            Sn  += NR[i0] - NR[i1];
            Szr += AR[i0] * AR[i1] + AI[i0] * AI[i1];
            Szi += AR[i0] * AI[i1] - AI[i0] * AR[i1];
        }
        E[q] = ct4[q] * Sn + 2.f * (mr4[q] * Szr - mi4[q] * Szi);
    }

    float o0 = post_b[0], o1 = post_b[1];
    #pragma unroll
    for (int q = 0; q < 4; ++q) {
        o0 = fmaf(post_w[q],     E[q], o0);
        o1 = fmaf(post_w[4 + q], E[q], o1);
    }
    float2 res; res.x = o0; res.y = o1;
    ((float2*)out)[row] = res;
}

extern "C" void kernel_launch(void* const* d_in, const int* in_sizes, int n_in,
                              void* d_out, int out_size) {
    const float* x      = (const float*)d_in[0];
    const float* pre_w  = (const float*)d_in[1];
    const float* pre_b  = (const float*)d_in[2];
    const float* u3p    = (const float*)d_in[3];
    const float* post_w = (const float*)d_in[4];
    const float* post_b = (const float*)d_in[5];
    float* out = (float*)d_out;

    int B = in_sizes[0] / KDIM;
    int grid = (B + ROWS - 1) / ROWS;
    qnet_kernel<<<grid, THREADS>>>(x, pre_w, pre_b, u3p, post_w, post_b, out, B);
}